// round 4
// baseline (speedup 1.0000x reference)
#include <cuda_runtime.h>
#include <math.h>

#define NP 64
#define NV4 1728      // 12^3
#define NV2 13824     // 24^3

#define C2_CS 131072  // comb2 [1,128,32,64,64]
#define C2_DS 4096
#define C2_HS 64
#define O1_CS 1048576 // out1 [1,64,64,128,128]
#define O1_DS 16384
#define O1_HS 128

#define OFF_RDEL 393216
#define OFF_RCL  2752512
#define OFF_RCD  2752640

// ---- scratch (static device globals; no allocation) ----
__device__ float g_vA[NP*64*NV4];     // conv1x1(fe1)+bias on 12^3 grid
__device__ float g_U [NP*64*NV2];     // upsampled pre-norm
__device__ float g_A1[NP*64];         // folded instnorm-1 scale
__device__ float g_B1[NP*64];         // folded instnorm-1 shift
__device__ float g_pre2[NP*64*NV2];   // conv2 pre-norm
__device__ float g_xT[32768*NP];      // pooled features, transposed [k][p]
__device__ float g_fc1p[64*NP*512];   // fc1 split-K partials [ks][m][o]

// ============================================================
// K1: RPN head. 2 voxels/thread, h[64] in regs, weights in smem.
// ============================================================
__global__ void __launch_bounds__(128) k_rpn(
    const float* __restrict__ c2,
    const float* __restrict__ w_rpn, const float* __restrict__ b_rpn,
    const float* __restrict__ w_rlog, const float* __restrict__ b_rlog,
    const float* __restrict__ w_rdel, const float* __restrict__ b_rdel,
    float* __restrict__ out)
{
    __shared__ float ws[64*128];
    __shared__ float w2[21*64];
    __shared__ float b2[21];
    __shared__ float br[64];
    int t = threadIdx.x;
    for (int i = t; i < 64*128; i += 128) ws[i] = w_rpn[i];
    for (int i = t; i < 3*64;   i += 128) w2[i] = w_rlog[i];
    for (int i = t; i < 18*64;  i += 128) w2[192+i] = w_rdel[i];
    if (t < 3) b2[t] = b_rlog[t];
    if (t >= 3 && t < 21) b2[t] = b_rdel[t-3];
    if (t < 64) br[t] = b_rpn[t];
    __syncthreads();

    int v0 = blockIdx.x*256 + t;
    int v1 = v0 + 128;
    float h0[64], h1[64];
    #pragma unroll
    for (int o = 0; o < 64; o++) { h0[o] = br[o]; h1[o] = br[o]; }
    for (int c = 0; c < 128; c++) {
        float x0 = c2[c*C2_CS + v0];
        float x1 = c2[c*C2_CS + v1];
        #pragma unroll
        for (int o = 0; o < 64; o++) {
            float w = ws[o*128 + c];
            h0[o] = fmaf(w, x0, h0[o]);
            h1[o] = fmaf(w, x1, h1[o]);
        }
    }
    #pragma unroll
    for (int o = 0; o < 64; o++) { h0[o] = fmaxf(h0[o], 0.f); h1[o] = fmaxf(h1[o], 0.f); }

    for (int j = 0; j < 21; j++) {
        float a0 = b2[j], a1 = b2[j];
        #pragma unroll
        for (int c = 0; c < 64; c++) {
            float w = w2[j*64 + c];
            a0 = fmaf(w, h0[c], a0);
            a1 = fmaf(w, h1[c], a1);
        }
        if (j < 3) { out[v0*3 + j] = a0; out[v1*3 + j] = a1; }
        else { out[OFF_RDEL + v0*18 + (j-3)] = a0; out[OFF_RDEL + v1*18 + (j-3)] = a1; }
    }
}

// ============================================================
// K2: conv1x1(fe1) on 12^3 grid (commuted before upsample), +bias
// ============================================================
__global__ void __launch_bounds__(128) k_convA(
    const float* __restrict__ c2, const int* __restrict__ props,
    const float* __restrict__ w_up2, const float* __restrict__ b_up2)
{
    __shared__ float ws[64*128];
    __shared__ float bs[64];
    __shared__ int sbase;
    int t = threadIdx.x, p = blockIdx.y;
    for (int i = t; i < 64*128; i += 128) ws[i] = w_up2[i];
    if (t < 64) bs[t] = b_up2[t];
    if (t == 0) {
        int z = props[p*7+1] >> 2, y = props[p*7+2] >> 2, x = props[p*7+3] >> 2;
        sbase = z*C2_DS + y*C2_HS + x;
    }
    __syncthreads();

    int vi0 = blockIdx.x*256 + t;
    int vi1 = vi0 + 128;
    bool a0 = vi0 < NV4, a1 = vi1 < NV4;
    int z0 = vi0/144, y0 = (vi0/12)%12, x0 = vi0%12;
    int z1 = vi1/144, y1 = (vi1/12)%12, x1 = vi1%12;
    int off0 = sbase + z0*C2_DS + y0*C2_HS + x0;
    int off1 = sbase + z1*C2_DS + y1*C2_HS + x1;

    float h0[64], h1[64];
    #pragma unroll
    for (int o = 0; o < 64; o++) { h0[o] = bs[o]; h1[o] = bs[o]; }
    for (int c = 0; c < 128; c++) {
        float xv0 = a0 ? c2[c*C2_CS + off0] : 0.f;
        float xv1 = a1 ? c2[c*C2_CS + off1] : 0.f;
        #pragma unroll
        for (int o = 0; o < 64; o++) {
            float w = ws[o*128 + c];
            h0[o] = fmaf(w, xv0, h0[o]);
            h1[o] = fmaf(w, xv1, h1[o]);
        }
    }
    #pragma unroll
    for (int o = 0; o < 64; o++) {
        if (a0) g_vA[(p*64 + o)*NV4 + vi0] = h0[o];
        if (a1) g_vA[(p*64 + o)*NV4 + vi1] = h1[o];
    }
}

// ============================================================
// K3: trilinear x2 upsample (align_corners) + instnorm-1 stats
//     one block per (p,o); source tile in smem; float4 stores
// ============================================================
__global__ void __launch_bounds__(256) k_up(
    const float* __restrict__ gup, const float* __restrict__ beup)
{
    __shared__ float s[NV4];
    __shared__ float red[256], red2[256];
    __shared__ int   lo[24];
    __shared__ float fw[24];
    int t = threadIdx.x, po = blockIdx.x;
    const float* src = g_vA + po*NV4;
    for (int i = t; i < NV4; i += 256) s[i] = src[i];
    if (t < 24) { int l = (t*11)/23; lo[t] = l; fw[t] = (float)(t*11)/23.f - (float)l; }
    __syncthreads();

    float sum = 0.f, ss = 0.f;
    float* dst = g_U + po*NV2;
    // 4 consecutive voxels per thread: X0 = (i0%24) in {0,4,...,20}, never
    // crosses a row, so Z/Y weights are shared across the quad.
    for (int i0 = t*4; i0 < NV2; i0 += 1024) {
        int Z = i0/576, Y = (i0/24)%24, X0 = i0%24;
        int lz = lo[Z], ly = lo[Y];
        float wz = fw[Z], wy = fw[Y];
        int hz = min(lz+1,11), hy = min(ly+1,11);
        int b00 = (lz*12+ly)*12, b01 = (lz*12+hy)*12;
        int b10 = (hz*12+ly)*12, b11 = (hz*12+hy)*12;
        float4 q;
        float* qp = (float*)&q;
        #pragma unroll
        for (int u = 0; u < 4; u++) {
            int X = X0 + u;
            int lx = lo[X], hx = min(lx+1,11);
            float wx = fw[X];
            float c000 = s[b00+lx], c001 = s[b00+hx];
            float c010 = s[b01+lx], c011 = s[b01+hx];
            float c100 = s[b10+lx], c101 = s[b10+hx];
            float c110 = s[b11+lx], c111 = s[b11+hx];
            float a00 = c000 + wx*(c001-c000);
            float a01 = c010 + wx*(c011-c010);
            float a10 = c100 + wx*(c101-c100);
            float a11 = c110 + wx*(c111-c110);
            float b0 = a00 + wy*(a01-a00);
            float b1 = a10 + wy*(a11-a10);
            float v  = b0 + wz*(b1-b0);
            qp[u] = v; sum += v; ss += v*v;
        }
        *(float4*)(dst + i0) = q;
    }
    red[t] = sum; red2[t] = ss; __syncthreads();
    for (int k = 128; k > 0; k >>= 1) {
        if (t < k) { red[t] += red[t+k]; red2[t] += red2[t+k]; }
        __syncthreads();
    }
    if (t == 0) {
        float mu  = red[0]  * (1.f/13824.f);
        float var = red2[0] * (1.f/13824.f) - mu*mu;
        float rs  = rsqrtf(var + 1e-5f);
        int o = po & 63;
        float a = gup[o]*rs;
        g_A1[po] = a;
        g_B1[po] = beup[o] - mu*a;
    }
}

// ============================================================
// K4: conv2 (128 -> 64) over 24^3, tiled GEMM 64o x 256v, 8x8/thread
//     thread (to,tv) owns output voxels tv*8..tv*8+7 (contiguous) ->
//     LDS.128 fragment reads + STG.128 epilogue stores
// ============================================================
__global__ void __launch_bounds__(256) k_conv2(
    const float* __restrict__ o1, const int* __restrict__ props,
    const float* __restrict__ w_back2, const float* __restrict__ b_back2)
{
    __shared__ float xs[8][256];
    __shared__ float wsh[8][64];
    __shared__ float sA[64], sB[64], sBias[64];
    __shared__ int sbase;
    int t = threadIdx.x, p = blockIdx.y;
    int vbase = blockIdx.x*256;
    if (t < 64) { sA[t] = g_A1[p*64+t]; sB[t] = g_B1[p*64+t]; sBias[t] = b_back2[t]; }
    if (t == 0) {
        int z = props[p*7+1] >> 1, y = props[p*7+2] >> 1, x = props[p*7+3] >> 1;
        sbase = z*O1_DS + y*O1_HS + x;
    }
    __syncthreads();

    int to = t >> 5, tv = t & 31;
    float acc[8][8];
    #pragma unroll
    for (int i = 0; i < 8; i++)
        #pragma unroll
        for (int j = 0; j < 8; j++) acc[i][j] = 0.f;

    int v = vbase + t;
    int Z = v/576, Y = (v/24)%24, X = v%24;
    int o1off = sbase + Z*O1_DS + Y*O1_HS + X;

    for (int kc = 0; kc < 128; kc += 8) {
        __syncthreads();
        #pragma unroll
        for (int i = 0; i < 8; i++) {
            int c = kc + i;
            float x;
            if (c < 64) x = fmaxf(fmaf(sA[c], g_U[(p*64 + c)*NV2 + v], sB[c]), 0.f);
            else        x = o1[(c-64)*O1_CS + o1off];
            xs[i][t] = x;
        }
        {
            int e = t*2;
            int kk = e >> 6, o = e & 63;
            wsh[kk][o]   = w_back2[o*128 + kc + kk];
            wsh[kk][o+1] = w_back2[(o+1)*128 + kc + kk];
        }
        __syncthreads();
        #pragma unroll
        for (int kk = 0; kk < 8; kk++) {
            float xr[8], wr[8];
            // 8 consecutive floats -> two LDS.128, conflict-free (32B/lane stride)
            *(float4*)(xr)     = *(const float4*)(&xs[kk][tv*8]);
            *(float4*)(xr + 4) = *(const float4*)(&xs[kk][tv*8 + 4]);
            #pragma unroll
            for (int i = 0; i < 8; i++) wr[i] = wsh[kk][to*8 + i];
            #pragma unroll
            for (int i = 0; i < 8; i++)
                #pragma unroll
                for (int j = 0; j < 8; j++)
                    acc[i][j] = fmaf(wr[i], xr[j], acc[i][j]);
        }
    }
    #pragma unroll
    for (int i = 0; i < 8; i++) {
        int o = to*8 + i;
        float b = sBias[o];
        float* dst = g_pre2 + (p*64 + o)*NV2 + vbase + tv*8;
        float4 q0, q1;
        q0.x = acc[i][0]+b; q0.y = acc[i][1]+b; q0.z = acc[i][2]+b; q0.w = acc[i][3]+b;
        q1.x = acc[i][4]+b; q1.y = acc[i][5]+b; q1.z = acc[i][6]+b; q1.w = acc[i][7]+b;
        *(float4*)(dst)     = q0;
        *(float4*)(dst + 4) = q1;
    }
}

// ============================================================
// K5: instnorm-2 stats + relu + 3^3 maxpool -> xT[k][p]
//     tile in dynamic smem (54 KB); float4 loads
// ============================================================
__global__ void __launch_bounds__(256) k_pool(
    const float* __restrict__ gback, const float* __restrict__ beback)
{
    extern __shared__ float s[];
    __shared__ float red[256], red2[256];
    __shared__ float saf, sbf;
    int t = threadIdx.x, po = blockIdx.x;
    const float* src = g_pre2 + po*NV2;
    float sum = 0.f, ss = 0.f;
    for (int i0 = t*4; i0 < NV2; i0 += 1024) {
        float4 q = *(const float4*)(src + i0);
        *(float4*)(s + i0) = q;
        sum += q.x + q.y + q.z + q.w;
        ss  += q.x*q.x + q.y*q.y + q.z*q.z + q.w*q.w;
    }
    red[t] = sum; red2[t] = ss; __syncthreads();
    for (int k = 128; k > 0; k >>= 1) {
        if (t < k) { red[t] += red[t+k]; red2[t] += red2[t+k]; }
        __syncthreads();
    }
    if (t == 0) {
        float mu  = red[0]  * (1.f/13824.f);
        float var = red2[0] * (1.f/13824.f) - mu*mu;
        float rs  = rsqrtf(var + 1e-5f);
        int o = po & 63;
        float a = gback[o]*rs;
        saf = a; sbf = beback[o] - mu*a;
    }
    __syncthreads();
    float a = saf, b = sbf;
    int p = po >> 6, o = po & 63;
    for (int j = t; j < 512; j += 256) {
        int pd = j >> 6, ph = (j >> 3) & 7, pw = j & 7;
        float mx = -3.4e38f, mn = 3.4e38f;
        #pragma unroll
        for (int dz = 0; dz < 3; dz++)
            #pragma unroll
            for (int dy = 0; dy < 3; dy++)
                #pragma unroll
                for (int dx = 0; dx < 3; dx++) {
                    float v = s[((pd*3+dz)*24 + (ph*3+dy))*24 + (pw*3+dx)];
                    mx = fmaxf(mx, v); mn = fminf(mn, v);
                }
        float u = (a >= 0.f) ? fmaf(a, mx, b) : fmaf(a, mn, b);
        g_xT[(o*512 + j)*NP + p] = fmaxf(u, 0.f);
    }
}

// ============================================================
// K6: fc1 split-K partials. tile M=64, O=128, Kchunk=512.
// ============================================================
__global__ void __launch_bounds__(128) k_fc1(const float* __restrict__ w)
{
    __shared__ float xs[8][64];
    __shared__ float wsh[8][128];
    int t = threadIdx.x;
    int obase = blockIdx.x*128;
    int kbase = blockIdx.y*512;
    int tm = t & 7, tog = t >> 3;
    float acc[8][8];
    #pragma unroll
    for (int i = 0; i < 8; i++)
        #pragma unroll
        for (int j = 0; j < 8; j++) acc[i][j] = 0.f;

    for (int kc = 0; kc < 512; kc += 8) {
        __syncthreads();
        #pragma unroll
        for (int i = 0; i < 4; i++) {
            int e = t + 128*i;
            xs[e >> 6][e & 63] = g_xT[(kbase + kc + (e >> 6))*NP + (e & 63)];
        }
        {
            const float* wp = w + (size_t)(obase + t)*32768 + kbase + kc;
            #pragma unroll
            for (int kk = 0; kk < 8; kk++) wsh[kk][t] = wp[kk];
        }
        __syncthreads();
        #pragma unroll
        for (int kk = 0; kk < 8; kk++) {
            float xr[8], wr[8];
            #pragma unroll
            for (int j = 0; j < 8; j++) xr[j] = xs[kk][tm + 8*j];
            #pragma unroll
            for (int i = 0; i < 8; i++) wr[i] = wsh[kk][tog*8 + i];
            #pragma unroll
            for (int i = 0; i < 8; i++)
                #pragma unroll
                for (int j = 0; j < 8; j++)
                    acc[i][j] = fmaf(wr[i], xr[j], acc[i][j]);
        }
    }
    int ks = blockIdx.y;
    #pragma unroll
    for (int j = 0; j < 8; j++) {
        int m = tm + 8*j;
        float* dst = g_fc1p + (ks*NP + m)*512 + obase + tog*8;
        float4 q0, q1;
        q0.x = acc[0][j]; q0.y = acc[1][j]; q0.z = acc[2][j]; q0.w = acc[3][j];
        q1.x = acc[4][j]; q1.y = acc[5][j]; q1.z = acc[6][j]; q1.w = acc[7][j];
        *(float4*)(dst)     = q0;
        *(float4*)(dst + 4) = q1;
    }
}

// ============================================================
// K7: reduce partials + bias + relu, fc2 + relu, heads. block per proposal.
// ============================================================
__global__ void __launch_bounds__(256) k_head(
    const float* __restrict__ b_fc1,
    const float* __restrict__ w_fc2, const float* __restrict__ b_fc2,
    const float* __restrict__ w_logit, const float* __restrict__ b_logit,
    const float* __restrict__ w_delta, const float* __restrict__ b_delta,
    float* __restrict__ out)
{
    __shared__ float x1[512];
    __shared__ float x2[256];
    int m = blockIdx.x, t = threadIdx.x;
    for (int o = t; o < 512; o += 256) {
        float s = b_fc1[o];
        for (int ks = 0; ks < 64; ks++) s += g_fc1p[(ks*NP + m)*512 + o];
        x1[o] = fmaxf(s, 0.f);
    }
    __syncthreads();
    {
        float s = b_fc2[t];
        const float* wp = w_fc2 + t*512;
        for (int k = 0; k < 512; k++) s = fmaf(wp[k], x1[k], s);
        x2[t] = fmaxf(s, 0.f);
    }
    __syncthreads();
    if (t < 14) {
        const float* wp = (t < 2) ? (w_logit + t*256) : (w_delta + (t-2)*256);
        float s = (t < 2) ? b_logit[t] : b_delta[t-2];
        for (int k = 0; k < 256; k++) s = fmaf(wp[k], x2[k], s);
        if (t < 2) out[OFF_RCL + m*2 + t] = s;
        else       out[OFF_RCD + m*12 + (t-2)] = s;
    }
}

extern "C" void kernel_launch(void* const* d_in, const int* in_sizes, int n_in,
                              void* d_out, int out_size)
{
    const float* out1    = (const float*)d_in[0];
    const float* comb2   = (const float*)d_in[1];
    const int*   props   = (const int*)  d_in[2];
    const float* w_rpn   = (const float*)d_in[3];
    const float* b_rpn   = (const float*)d_in[4];
    const float* w_rlog  = (const float*)d_in[5];
    const float* b_rlog  = (const float*)d_in[6];
    const float* w_rdel  = (const float*)d_in[7];
    const float* b_rdel  = (const float*)d_in[8];
    const float* w_up2   = (const float*)d_in[9];
    const float* b_up2   = (const float*)d_in[10];
    const float* g_up2   = (const float*)d_in[11];
    const float* be_up2  = (const float*)d_in[12];
    const float* w_back2 = (const float*)d_in[13];
    const float* b_back2 = (const float*)d_in[14];
    const float* g_back2 = (const float*)d_in[15];
    const float* be_back2= (const float*)d_in[16];
    const float* w_fc1   = (const float*)d_in[17];
    const float* b_fc1   = (const float*)d_in[18];
    const float* w_fc2   = (const float*)d_in[19];
    const float* b_fc2   = (const float*)d_in[20];
    const float* w_logit = (const float*)d_in[21];
    const float* b_logit = (const float*)d_in[22];
    const float* w_delta = (const float*)d_in[23];
    const float* b_delta = (const float*)d_in[24];
    float* out = (float*)d_out;

    cudaFuncSetAttribute(k_pool, cudaFuncAttributeMaxDynamicSharedMemorySize, NV2*4);

    k_rpn  <<<512, 128>>>(comb2, w_rpn, b_rpn, w_rlog, b_rlog, w_rdel, b_rdel, out);
    k_convA<<<dim3(7, NP), 128>>>(comb2, props, w_up2, b_up2);
    k_up   <<<NP*64, 256>>>(g_up2, be_up2);
    k_conv2<<<dim3(54, NP), 256>>>(out1, props, w_back2, b_back2);
    k_pool <<<NP*64, 256, NV2*4>>>(g_back2, be_back2);
    k_fc1  <<<dim3(4, 64), 128>>>(w_fc1);
    k_head <<<NP, 256>>>(b_fc1, w_fc2, b_fc2, w_logit, b_logit, w_delta, b_delta, out);
}

// round 16
// speedup vs baseline: 1.1755x; 1.1755x over previous
#include <cuda_runtime.h>
#include <math.h>

#define NP 64
#define NV4 1728      // 12^3
#define NV2 13824     // 24^3

#define C2_CS 131072  // comb2 [1,128,32,64,64]
#define C2_DS 4096
#define C2_HS 64
#define O1_CS 1048576 // out1 [1,64,64,128,128]
#define O1_DS 16384
#define O1_HS 128

#define OFF_RDEL 393216
#define OFF_RCL  2752512
#define OFF_RCD  2752640

// ---- scratch (static device globals; no allocation) ----
__device__ float g_vA[NP*64*NV4];     // conv1x1(fe1)+bias on 12^3 grid
__device__ float g_U [NP*64*NV2];     // upsampled pre-norm
__device__ float g_A1[NP*64];         // folded instnorm-1 scale
__device__ float g_B1[NP*64];         // folded instnorm-1 shift
__device__ float g_pre2[NP*64*NV2];   // conv2 pre-norm
__device__ float g_xT[32768*NP];      // pooled features, transposed [k][p]
__device__ float g_fc1p[64*NP*512];   // fc1 split-K partials [ks][m][o]

// ============================================================
// K1: RPN head. 256 threads, 1 voxel/thread, h[64] in regs.
// ============================================================
__global__ void __launch_bounds__(256) k_rpn(
    const float* __restrict__ c2,
    const float* __restrict__ w_rpn, const float* __restrict__ b_rpn,
    const float* __restrict__ w_rlog, const float* __restrict__ b_rlog,
    const float* __restrict__ w_rdel, const float* __restrict__ b_rdel,
    float* __restrict__ out)
{
    __shared__ float ws[64*128];
    __shared__ float w2[21*64];
    __shared__ float b2[21];
    __shared__ float br[64];
    int t = threadIdx.x;
    for (int i = t; i < 64*128; i += 256) ws[i] = w_rpn[i];
    for (int i = t; i < 3*64;   i += 256) w2[i] = w_rlog[i];
    for (int i = t; i < 18*64;  i += 256) w2[192+i] = w_rdel[i];
    if (t < 3) b2[t] = b_rlog[t];
    if (t >= 3 && t < 21) b2[t] = b_rdel[t-3];
    if (t < 64) br[t] = b_rpn[t];
    __syncthreads();

    int v = blockIdx.x*256 + t;
    float h[64];
    #pragma unroll
    for (int o = 0; o < 64; o++) h[o] = br[o];
    #pragma unroll 4
    for (int c = 0; c < 128; c++) {
        float x = c2[c*C2_CS + v];
        #pragma unroll
        for (int o = 0; o < 64; o++)
            h[o] = fmaf(ws[o*128 + c], x, h[o]);
    }
    #pragma unroll
    for (int o = 0; o < 64; o++) h[o] = fmaxf(h[o], 0.f);

    for (int j = 0; j < 21; j++) {
        float a = b2[j];
        #pragma unroll
        for (int c = 0; c < 64; c++)
            a = fmaf(w2[j*64 + c], h[c], a);
        if (j < 3) out[v*3 + j] = a;
        else       out[OFF_RDEL + v*18 + (j-3)] = a;
    }
}

// ============================================================
// K2: conv1x1(fe1) on 12^3 grid (commuted before upsample), +bias
//     256 threads, 1 voxel/thread.
// ============================================================
__global__ void __launch_bounds__(256) k_convA(
    const float* __restrict__ c2, const int* __restrict__ props,
    const float* __restrict__ w_up2, const float* __restrict__ b_up2)
{
    __shared__ float ws[64*128];
    __shared__ float bs[64];
    __shared__ int sbase;
    int t = threadIdx.x, p = blockIdx.y;
    for (int i = t; i < 64*128; i += 256) ws[i] = w_up2[i];
    if (t < 64) bs[t] = b_up2[t];
    if (t == 0) {
        int z = props[p*7+1] >> 2, y = props[p*7+2] >> 2, x = props[p*7+3] >> 2;
        sbase = z*C2_DS + y*C2_HS + x;
    }
    __syncthreads();

    int vi = blockIdx.x*256 + t;
    bool act = vi < NV4;
    int z0 = vi/144, y0 = (vi/12)%12, x0 = vi%12;
    int off = sbase + z0*C2_DS + y0*C2_HS + x0;

    float h[64];
    #pragma unroll
    for (int o = 0; o < 64; o++) h[o] = bs[o];
    #pragma unroll 4
    for (int c = 0; c < 128; c++) {
        float xv = act ? c2[c*C2_CS + off] : 0.f;
        #pragma unroll
        for (int o = 0; o < 64; o++)
            h[o] = fmaf(ws[o*128 + c], xv, h[o]);
    }
    if (act) {
        #pragma unroll
        for (int o = 0; o < 64; o++)
            g_vA[(p*64 + o)*NV4 + vi] = h[o];
    }
}

// ============================================================
// K3: trilinear x2 upsample (align_corners) + instnorm-1 stats
//     one block per (p,o); source tile in smem; float4 stores
// ============================================================
__global__ void __launch_bounds__(256) k_up(
    const float* __restrict__ gup, const float* __restrict__ beup)
{
    __shared__ float s[NV4];
    __shared__ float red[256], red2[256];
    __shared__ int   lo[24];
    __shared__ float fw[24];
    int t = threadIdx.x, po = blockIdx.x;
    const float* src = g_vA + po*NV4;
    for (int i = t; i < NV4; i += 256) s[i] = src[i];
    if (t < 24) { int l = (t*11)/23; lo[t] = l; fw[t] = (float)(t*11)/23.f - (float)l; }
    __syncthreads();

    float sum = 0.f, ss = 0.f;
    float* dst = g_U + po*NV2;
    for (int i0 = t*4; i0 < NV2; i0 += 1024) {
        int Z = i0/576, Y = (i0/24)%24, X0 = i0%24;
        int lz = lo[Z], ly = lo[Y];
        float wz = fw[Z], wy = fw[Y];
        int hz = min(lz+1,11), hy = min(ly+1,11);
        int b00 = (lz*12+ly)*12, b01 = (lz*12+hy)*12;
        int b10 = (hz*12+ly)*12, b11 = (hz*12+hy)*12;
        float4 q;
        float* qp = (float*)&q;
        #pragma unroll
        for (int u = 0; u < 4; u++) {
            int X = X0 + u;
            int lx = lo[X], hx = min(lx+1,11);
            float wx = fw[X];
            float c000 = s[b00+lx], c001 = s[b00+hx];
            float c010 = s[b01+lx], c011 = s[b01+hx];
            float c100 = s[b10+lx], c101 = s[b10+hx];
            float c110 = s[b11+lx], c111 = s[b11+hx];
            float a00 = c000 + wx*(c001-c000);
            float a01 = c010 + wx*(c011-c010);
            float a10 = c100 + wx*(c101-c100);
            float a11 = c110 + wx*(c111-c110);
            float b0 = a00 + wy*(a01-a00);
            float b1 = a10 + wy*(a11-a10);
            float v  = b0 + wz*(b1-b0);
            qp[u] = v; sum += v; ss += v*v;
        }
        *(float4*)(dst + i0) = q;
    }
    red[t] = sum; red2[t] = ss; __syncthreads();
    for (int k = 128; k > 0; k >>= 1) {
        if (t < k) { red[t] += red[t+k]; red2[t] += red2[t+k]; }
        __syncthreads();
    }
    if (t == 0) {
        float mu  = red[0]  * (1.f/13824.f);
        float var = red2[0] * (1.f/13824.f) - mu*mu;
        float rs  = rsqrtf(var + 1e-5f);
        int o = po & 63;
        float a = gup[o]*rs;
        g_A1[po] = a;
        g_B1[po] = beup[o] - mu*a;
    }
}

// ============================================================
// K4: conv2 (128 -> 64), software-pipelined double-buffered GEMM.
//     64o x 256v tile, 8x8/thread. Register prefetch of next K-tile
//     overlaps global latency with FMA work. One barrier per K-tile.
// ============================================================
__global__ void __launch_bounds__(256) k_conv2(
    const float* __restrict__ o1, const int* __restrict__ props,
    const float* __restrict__ w_back2, const float* __restrict__ b_back2)
{
    __shared__ __align__(16) float xs[2][8][256];
    __shared__ __align__(16) float wsh[2][8][64];
    __shared__ float sA[64], sB[64], sBias[64];
    __shared__ int sbase;
    int t = threadIdx.x, p = blockIdx.y;
    int vbase = blockIdx.x*256;
    if (t < 64) { sA[t] = g_A1[p*64+t]; sB[t] = g_B1[p*64+t]; sBias[t] = b_back2[t]; }
    if (t == 0) {
        int z = props[p*7+1] >> 1, y = props[p*7+2] >> 1, x = props[p*7+3] >> 1;
        sbase = z*O1_DS + y*O1_HS + x;
    }
    __syncthreads();

    int to = t >> 5, tv = t & 31;
    int wkk = (t*2) >> 6, wo = (t*2) & 63;   // weight-fill coords (512 elems / 256 thr)

    float acc[8][8];
    #pragma unroll
    for (int i = 0; i < 8; i++)
        #pragma unroll
        for (int j = 0; j < 8; j++) acc[i][j] = 0.f;

    int v = vbase + t;
    int Z = v/576, Y = (v/24)%24, X = v%24;
    int o1off = sbase + Z*O1_DS + Y*O1_HS + X;

    // ---- prologue: prefetch K-tile 0 into registers ----
    float xn[8], wn0, wn1;
    {
        const float* up = g_U + (p*64)*NV2 + v;   // tile 0 is all c<64
        #pragma unroll
        for (int i = 0; i < 8; i++)
            xn[i] = fmaxf(fmaf(sA[i], up[i*NV2], sB[i]), 0.f);
        wn0 = w_back2[wo*128 + wkk];
        wn1 = w_back2[(wo+1)*128 + wkk];
    }

    for (int kt = 0; kt < 16; kt++) {
        int buf = kt & 1;
        // commit prefetched tile to smem
        #pragma unroll
        for (int i = 0; i < 8; i++) xs[buf][i][t] = xn[i];
        wsh[buf][wkk][wo]   = wn0;
        wsh[buf][wkk][wo+1] = wn1;
        __syncthreads();

        // issue next tile's global loads (latency hidden by math below)
        if (kt < 15) {
            int kc = (kt+1)*8;
            if (kc < 64) {
                const float* up = g_U + (p*64 + kc)*NV2 + v;
                #pragma unroll
                for (int i = 0; i < 8; i++)
                    xn[i] = fmaxf(fmaf(sA[kc+i], up[i*NV2], sB[kc+i]), 0.f);
            } else {
                const float* op = o1 + (kc-64)*O1_CS + o1off;
                #pragma unroll
                for (int i = 0; i < 8; i++)
                    xn[i] = op[i*O1_CS];
            }
            wn0 = w_back2[wo*128 + kc + wkk];
            wn1 = w_back2[(wo+1)*128 + kc + wkk];
        }

        // math on current buffer
        #pragma unroll
        for (int kk = 0; kk < 8; kk++) {
            float xr[8], wr[8];
            *(float4*)(xr)     = *(const float4*)(&xs[buf][kk][tv*8]);
            *(float4*)(xr + 4) = *(const float4*)(&xs[buf][kk][tv*8 + 4]);
            *(float4*)(wr)     = *(const float4*)(&wsh[buf][kk][to*8]);
            *(float4*)(wr + 4) = *(const float4*)(&wsh[buf][kk][to*8 + 4]);
            #pragma unroll
            for (int i = 0; i < 8; i++)
                #pragma unroll
                for (int j = 0; j < 8; j++)
                    acc[i][j] = fmaf(wr[i], xr[j], acc[i][j]);
        }
    }
    #pragma unroll
    for (int i = 0; i < 8; i++) {
        int o = to*8 + i;
        float b = sBias[o];
        float* dst = g_pre2 + (p*64 + o)*NV2 + vbase + tv*8;
        float4 q0, q1;
        q0.x = acc[i][0]+b; q0.y = acc[i][1]+b; q0.z = acc[i][2]+b; q0.w = acc[i][3]+b;
        q1.x = acc[i][4]+b; q1.y = acc[i][5]+b; q1.z = acc[i][6]+b; q1.w = acc[i][7]+b;
        *(float4*)(dst)     = q0;
        *(float4*)(dst + 4) = q1;
    }
}

// ============================================================
// K5: instnorm-2 stats + relu + 3^3 maxpool -> xT[k][p]
//     tile in dynamic smem (54 KB); float4 loads
// ============================================================
__global__ void __launch_bounds__(256) k_pool(
    const float* __restrict__ gback, const float* __restrict__ beback)
{
    extern __shared__ float s[];
    __shared__ float red[256], red2[256];
    __shared__ float saf, sbf;
    int t = threadIdx.x, po = blockIdx.x;
    const float* src = g_pre2 + po*NV2;
    float sum = 0.f, ss = 0.f;
    for (int i0 = t*4; i0 < NV2; i0 += 1024) {
        float4 q = *(const float4*)(src + i0);
        *(float4*)(s + i0) = q;
        sum += q.x + q.y + q.z + q.w;
        ss  += q.x*q.x + q.y*q.y + q.z*q.z + q.w*q.w;
    }
    red[t] = sum; red2[t] = ss; __syncthreads();
    for (int k = 128; k > 0; k >>= 1) {
        if (t < k) { red[t] += red[t+k]; red2[t] += red2[t+k]; }
        __syncthreads();
    }
    if (t == 0) {
        float mu  = red[0]  * (1.f/13824.f);
        float var = red2[0] * (1.f/13824.f) - mu*mu;
        float rs  = rsqrtf(var + 1e-5f);
        int o = po & 63;
        float a = gback[o]*rs;
        saf = a; sbf = beback[o] - mu*a;
    }
    __syncthreads();
    float a = saf, b = sbf;
    int p = po >> 6, o = po & 63;
    for (int j = t; j < 512; j += 256) {
        int pd = j >> 6, ph = (j >> 3) & 7, pw = j & 7;
        float mx = -3.4e38f, mn = 3.4e38f;
        #pragma unroll
        for (int dz = 0; dz < 3; dz++)
            #pragma unroll
            for (int dy = 0; dy < 3; dy++)
                #pragma unroll
                for (int dx = 0; dx < 3; dx++) {
                    float v = s[((pd*3+dz)*24 + (ph*3+dy))*24 + (pw*3+dx)];
                    mx = fmaxf(mx, v); mn = fminf(mn, v);
                }
        float u = (a >= 0.f) ? fmaf(a, mx, b) : fmaf(a, mn, b);
        g_xT[(o*512 + j)*NP + p] = fmaxf(u, 0.f);
    }
}

// ============================================================
// K6: fc1 split-K partials. tile M=64, O=128, Kchunk=512.
// ============================================================
__global__ void __launch_bounds__(128) k_fc1(const float* __restrict__ w)
{
    __shared__ float xs[8][64];
    __shared__ float wsh[8][128];
    int t = threadIdx.x;
    int obase = blockIdx.x*128;
    int kbase = blockIdx.y*512;
    int tm = t & 7, tog = t >> 3;
    float acc[8][8];
    #pragma unroll
    for (int i = 0; i < 8; i++)
        #pragma unroll
        for (int j = 0; j < 8; j++) acc[i][j] = 0.f;

    for (int kc = 0; kc < 512; kc += 8) {
        __syncthreads();
        #pragma unroll
        for (int i = 0; i < 4; i++) {
            int e = t + 128*i;
            xs[e >> 6][e & 63] = g_xT[(kbase + kc + (e >> 6))*NP + (e & 63)];
        }
        {
            const float* wp = w + (size_t)(obase + t)*32768 + kbase + kc;
            #pragma unroll
            for (int kk = 0; kk < 8; kk++) wsh[kk][t] = wp[kk];
        }
        __syncthreads();
        #pragma unroll
        for (int kk = 0; kk < 8; kk++) {
            float xr[8], wr[8];
            #pragma unroll
            for (int j = 0; j < 8; j++) xr[j] = xs[kk][tm + 8*j];
            #pragma unroll
            for (int i = 0; i < 8; i++) wr[i] = wsh[kk][tog*8 + i];
            #pragma unroll
            for (int i = 0; i < 8; i++)
                #pragma unroll
                for (int j = 0; j < 8; j++)
                    acc[i][j] = fmaf(wr[i], xr[j], acc[i][j]);
        }
    }
    int ks = blockIdx.y;
    #pragma unroll
    for (int j = 0; j < 8; j++) {
        int m = tm + 8*j;
        float* dst = g_fc1p + (ks*NP + m)*512 + obase + tog*8;
        float4 q0, q1;
        q0.x = acc[0][j]; q0.y = acc[1][j]; q0.z = acc[2][j]; q0.w = acc[3][j];
        q1.x = acc[4][j]; q1.y = acc[5][j]; q1.z = acc[6][j]; q1.w = acc[7][j];
        *(float4*)(dst)     = q0;
        *(float4*)(dst + 4) = q1;
    }
}

// ============================================================
// K7: reduce partials + bias + relu, fc2 + relu, heads. block per proposal.
// ============================================================
__global__ void __launch_bounds__(256) k_head(
    const float* __restrict__ b_fc1,
    const float* __restrict__ w_fc2, const float* __restrict__ b_fc2,
    const float* __restrict__ w_logit, const float* __restrict__ b_logit,
    const float* __restrict__ w_delta, const float* __restrict__ b_delta,
    float* __restrict__ out)
{
    __shared__ float x1[512];
    __shared__ float x2[256];
    int m = blockIdx.x, t = threadIdx.x;
    for (int o = t; o < 512; o += 256) {
        float s = b_fc1[o];
        for (int ks = 0; ks < 64; ks++) s += g_fc1p[(ks*NP + m)*512 + o];
        x1[o] = fmaxf(s, 0.f);
    }
    __syncthreads();
    {
        float s = b_fc2[t];
        const float* wp = w_fc2 + t*512;
        for (int k = 0; k < 512; k++) s = fmaf(wp[k], x1[k], s);
        x2[t] = fmaxf(s, 0.f);
    }
    __syncthreads();
    if (t < 14) {
        const float* wp = (t < 2) ? (w_logit + t*256) : (w_delta + (t-2)*256);
        float s = (t < 2) ? b_logit[t] : b_delta[t-2];
        for (int k = 0; k < 256; k++) s = fmaf(wp[k], x2[k], s);
        if (t < 2) out[OFF_RCL + m*2 + t] = s;
        else       out[OFF_RCD + m*12 + (t-2)] = s;
    }
}

extern "C" void kernel_launch(void* const* d_in, const int* in_sizes, int n_in,
                              void* d_out, int out_size)
{
    const float* out1    = (const float*)d_in[0];
    const float* comb2   = (const float*)d_in[1];
    const int*   props   = (const int*)  d_in[2];
    const float* w_rpn   = (const float*)d_in[3];
    const float* b_rpn   = (const float*)d_in[4];
    const float* w_rlog  = (const float*)d_in[5];
    const float* b_rlog  = (const float*)d_in[6];
    const float* w_rdel  = (const float*)d_in[7];
    const float* b_rdel  = (const float*)d_in[8];
    const float* w_up2   = (const float*)d_in[9];
    const float* b_up2   = (const float*)d_in[10];
    const float* g_up2   = (const float*)d_in[11];
    const float* be_up2  = (const float*)d_in[12];
    const float* w_back2 = (const float*)d_in[13];
    const float* b_back2 = (const float*)d_in[14];
    const float* g_back2 = (const float*)d_in[15];
    const float* be_back2= (const float*)d_in[16];
    const float* w_fc1   = (const float*)d_in[17];
    const float* b_fc1   = (const float*)d_in[18];
    const float* w_fc2   = (const float*)d_in[19];
    const float* b_fc2   = (const float*)d_in[20];
    const float* w_logit = (const float*)d_in[21];
    const float* b_logit = (const float*)d_in[22];
    const float* w_delta = (const float*)d_in[23];
    const float* b_delta = (const float*)d_in[24];
    float* out = (float*)d_out;

    cudaFuncSetAttribute(k_pool, cudaFuncAttributeMaxDynamicSharedMemorySize, NV2*4);

    k_rpn  <<<512, 256>>>(comb2, w_rpn, b_rpn, w_rlog, b_rlog, w_rdel, b_rdel, out);
    k_convA<<<dim3(7, NP), 256>>>(comb2, props, w_up2, b_up2);
    k_up   <<<NP*64, 256>>>(g_up2, be_up2);
    k_conv2<<<dim3(54, NP), 256>>>(out1, props, w_back2, b_back2);
    k_pool <<<NP*64, 256, NV2*4>>>(g_back2, be_back2);
    k_fc1  <<<dim3(4, 64), 128>>>(w_fc1);
    k_head <<<NP, 256>>>(b_fc1, w_fc2, b_fc2, w_logit, b_logit, w_delta, b_delta, out);
}